// round 1
// baseline (speedup 1.0000x reference)
#include <cuda_runtime.h>
#include <cstdint>

// ---------------- constants ----------------
#define LN2f    0.6931471805599453f
#define CSSf    0.7071067811865476f   // 1/sqrt(2)
#define CVVf    0.4082482904638631f   // 1/sqrt(6)
#define CSVf    0.7071067811865476f   // 1/sqrt(2)
#define INV8f   0.125f                // 1/sqrt(64)
#define INVS32f 0.17677669529663687f  // 1/sqrt(32)
#define INVS8f  0.3535533905932738f   // 1/sqrt(8)

#define NMAXN 5000
#define EMAXE 131072

// ---------------- scratch (static device arrays; no allocation) ----------------
__device__ float g_n0[(size_t)NMAXN * 256];
__device__ float g_h [(size_t)NMAXN * 256];
__device__ float g_pair[(size_t)EMAXE * 256];

__device__ __forceinline__ float silu_f(float x) { return x / (1.f + __expf(-x)); }
__device__ __forceinline__ float ssp_f(float x) {
    return fmaxf(x, 0.f) + log1pf(__expf(-fabsf(x))) - LN2f;
}

// warp e3nn_linear: xin = shared 256 merged (s[64] | v[64*3]); writes merged 256 to global
__device__ __forceinline__ void e3nn_warp(const float* __restrict__ xin,
                                          const float* __restrict__ W0s,
                                          const float* __restrict__ W1s,
                                          const float* __restrict__ b0s,
                                          float* __restrict__ outg,
                                          const float* __restrict__ addg, // may be null
                                          int lane)
{
    float a0 = 0.f, a1 = 0.f;
    #pragma unroll 4
    for (int u = 0; u < 64; ++u) {
        float s = xin[u];
        a0 += s * W0s[u * 64 + lane];
        a1 += s * W0s[u * 64 + lane + 32];
    }
    a0 = a0 * INV8f + b0s[lane];
    a1 = a1 * INV8f + b0s[lane + 32];
    if (addg) { a0 += addg[lane]; a1 += addg[lane + 32]; }
    outg[lane] = a0;
    outg[lane + 32] = a1;

    float v00 = 0.f, v01 = 0.f, v02 = 0.f, v10 = 0.f, v11 = 0.f, v12 = 0.f;
    #pragma unroll 4
    for (int u = 0; u < 64; ++u) {
        float w0 = W1s[u * 64 + lane];
        float w1 = W1s[u * 64 + lane + 32];
        float e0 = xin[64 + 3 * u + 0];
        float e1 = xin[64 + 3 * u + 1];
        float e2 = xin[64 + 3 * u + 2];
        v00 += e0 * w0; v01 += e1 * w0; v02 += e2 * w0;
        v10 += e0 * w1; v11 += e1 * w1; v12 += e2 * w1;
    }
    int w2 = lane + 32;
    if (addg) {
        outg[64 + 3 * lane + 0] = v00 * INV8f + addg[64 + 3 * lane + 0];
        outg[64 + 3 * lane + 1] = v01 * INV8f + addg[64 + 3 * lane + 1];
        outg[64 + 3 * lane + 2] = v02 * INV8f + addg[64 + 3 * lane + 2];
        outg[64 + 3 * w2 + 0]   = v10 * INV8f + addg[64 + 3 * w2 + 0];
        outg[64 + 3 * w2 + 1]   = v11 * INV8f + addg[64 + 3 * w2 + 1];
        outg[64 + 3 * w2 + 2]   = v12 * INV8f + addg[64 + 3 * w2 + 2];
    } else {
        outg[64 + 3 * lane + 0] = v00 * INV8f;
        outg[64 + 3 * lane + 1] = v01 * INV8f;
        outg[64 + 3 * lane + 2] = v02 * INV8f;
        outg[64 + 3 * w2 + 0]   = v10 * INV8f;
        outg[64 + 3 * w2 + 1]   = v11 * INV8f;
        outg[64 + 3 * w2 + 2]   = v12 * INV8f;
    }
}

// warp 128->128 matvec from shared weights, optional silu
template<bool ACT>
__device__ __forceinline__ void mv128_warp(const float* __restrict__ Ws,
                                           const float* __restrict__ in,
                                           const float* __restrict__ bs,
                                           float* __restrict__ out, int lane)
{
    float a0 = 0.f, a1 = 0.f, a2 = 0.f, a3 = 0.f;
    #pragma unroll 4
    for (int k = 0; k < 128; ++k) {
        float c = in[k];
        const float* wr = Ws + k * 128;
        a0 += c * wr[lane];
        a1 += c * wr[lane + 32];
        a2 += c * wr[lane + 64];
        a3 += c * wr[lane + 96];
    }
    a0 += bs[lane]; a1 += bs[lane + 32]; a2 += bs[lane + 64]; a3 += bs[lane + 96];
    if (ACT) { a0 = silu_f(a0); a1 = silu_f(a1); a2 = silu_f(a2); a3 = silu_f(a3); }
    out[lane] = a0; out[lane + 32] = a1; out[lane + 64] = a2; out[lane + 96] = a3;
}

// ======================= kernel 1: per-node precompute =======================
// g_n0 = e3nn_linear(node_attr, Wli0, Wli1, bli0)
// g_h  = e3nn_linear(norm_gate(node_attr, ng1), Wlp0, Wlp1, blp0)
__global__ void __launch_bounds__(256) node_kernel(
    const float* __restrict__ node_attr, int N,
    const float* __restrict__ Wli0, const float* __restrict__ Wli1, const float* __restrict__ bli0,
    const float* __restrict__ W1, const float* __restrict__ b1,
    const float* __restrict__ W2, const float* __restrict__ b2,
    const float* __restrict__ Wlp0, const float* __restrict__ Wlp1, const float* __restrict__ blp0)
{
    extern __shared__ float sh[];
    float* sWli0 = sh;              // 4096
    float* sWli1 = sh + 4096;       // 4096
    float* sWlp0 = sh + 8192;       // 4096
    float* sWlp1 = sh + 12288;      // 4096
    float* sW1   = sh + 16384;      // 16384
    float* sW2   = sh + 32768;      // 16384
    float* sbias = sh + 49152;      // 384: [bli0 64][b1 128][b2 128][blp0 64]
    float* sstage= sh + 49536;      // 8 * 1024

    int tid = threadIdx.x;
    for (int i = tid; i < 4096; i += 256) {
        sWli0[i] = Wli0[i]; sWli1[i] = Wli1[i];
        sWlp0[i] = Wlp0[i]; sWlp1[i] = Wlp1[i];
    }
    for (int i = tid; i < 16384; i += 256) { sW1[i] = W1[i]; sW2[i] = W2[i]; }
    if (tid < 64)  { sbias[tid] = bli0[tid]; sbias[320 + tid] = blp0[tid]; }
    if (tid < 128) { sbias[64 + tid] = b1[tid]; sbias[192 + tid] = b2[tid]; }
    __syncthreads();

    const float* sbli0 = sbias;
    const float* sb1   = sbias + 64;
    const float* sb2   = sbias + 192;
    const float* sblp0 = sbias + 320;

    int warp = tid >> 5, lane = tid & 31;
    int gw = blockIdx.x * 8 + warp;
    int nwarps = gridDim.x * 8;
    float* st  = sstage + warp * 1024;
    float* x   = st;          // 256
    float* cat = st + 256;    // 128
    float* g1  = st + 384;    // 128
    float* gv  = st + 512;    // 128
    float* hg  = st + 640;    // 256

    for (int node = gw; node < N; node += nwarps) {
        const float* xg = node_attr + (size_t)node * 256;
        for (int i = lane; i < 256; i += 32) x[i] = xg[i];
        __syncwarp();

        // n0
        e3nn_warp(x, sWli0, sWli1, sbli0, g_n0 + (size_t)node * 256, nullptr, lane);

        // norm_gate cat
        #pragma unroll
        for (int r = 0; r < 2; ++r) {
            int u = lane + 32 * r;
            cat[u] = x[u];
            float v0 = x[64 + 3 * u], v1 = x[64 + 3 * u + 1], v2 = x[64 + 3 * u + 2];
            cat[64 + u] = sqrtf(v0 * v0 + v1 * v1 + v2 * v2);
        }
        __syncwarp();
        mv128_warp<true >(sW1, cat, sb1, g1, lane);
        __syncwarp();
        mv128_warp<false>(sW2, g1, sb2, gv, lane);
        __syncwarp();
        // gated merged vector
        #pragma unroll
        for (int r = 0; r < 2; ++r) {
            int u = lane + 32 * r;
            hg[u] = gv[u];
            float gu = gv[64 + u];
            hg[64 + 3 * u + 0] = x[64 + 3 * u + 0] * gu;
            hg[64 + 3 * u + 1] = x[64 + 3 * u + 1] * gu;
            hg[64 + 3 * u + 2] = x[64 + 3 * u + 2] * gu;
        }
        __syncwarp();
        e3nn_warp(hg, sWlp0, sWlp1, sblp0, g_h + (size_t)node * 256, nullptr, lane);
        __syncwarp();
    }
}

// ======================= kernel 2: edge phase A =======================
// g_pair[e] = tensor-product pair features (pre-gate)
__global__ void __launch_bounds__(512) edgeA_kernel(
    const int* __restrict__ eidx, int E,
    const float* __restrict__ edge_attr,
    const float* __restrict__ A1, const float* __restrict__ a1b,
    const float* __restrict__ A2, const float* __restrict__ a2b,
    const float* __restrict__ F1, const float* __restrict__ F2)
{
    extern __shared__ float sh[];
    float* sA1 = sh;             // 8192 (128x64)
    float* sA2 = sh + 8192;      // 16384 (64x256)
    float* sF1 = sh + 24576;     // 256 (32x8)
    float* sF2 = sh + 24832;     // 2048 (8x256)
    float* sb  = sh + 26880;     // 320: [a1b 64][a2b 256]
    float* sstage = sh + 27200;  // 16 * 1024

    int tid = threadIdx.x;
    for (int i = tid; i < 8192; i += 512)  sA1[i] = A1[i];
    for (int i = tid; i < 16384; i += 512) sA2[i] = A2[i];
    if (tid < 256) sF1[tid] = F1[tid];
    for (int i = tid; i < 2048; i += 512)  sF2[i] = F2[i];
    if (tid < 64)  sb[tid] = a1b[tid];
    if (tid < 256) sb[64 + tid] = a2b[tid];
    __syncthreads();
    const float* sa1b = sb;
    const float* sa2b = sb + 64;

    int warp = tid >> 5, lane = tid & 31;
    int gw = blockIdx.x * 16 + warp;
    int nwarps = gridDim.x * 16;
    float* st   = sstage + warp * 1024;
    float* bufd = st;         // 256 (n0[dst] -> h[dst])
    float* bufs = st + 256;   // 256 (n0[src] -> h[src])
    float* wbuf = st + 512;   // 256
    float* s0   = st + 768;   // 128
    float* t    = st + 896;   // 64
    float* u8   = st + 960;   // 8

    for (int e = gw; e < E; e += nwarps) {
        int dst = eidx[e];
        int src = eidx[E + e];
        const float* nd = g_n0 + (size_t)dst * 256;
        const float* ns = g_n0 + (size_t)src * 256;
        for (int i = lane; i < 256; i += 32) { bufd[i] = nd[i]; bufs[i] = ns[i]; }
        __syncwarp();

        // s0 = [0.5*(sd+ss), ip/3]
        #pragma unroll
        for (int r = 0; r < 2; ++r) {
            int u = lane + 32 * r;
            s0[u] = 0.5f * (bufd[u] + bufs[u]);
            float ip = bufd[64 + 3 * u + 0] * bufs[64 + 3 * u + 0]
                     + bufd[64 + 3 * u + 1] * bufs[64 + 3 * u + 1]
                     + bufd[64 + 3 * u + 2] * bufs[64 + 3 * u + 2];
            s0[64 + u] = ip * (1.f / 3.f);
        }
        // edge MLP first stage: 8 lanes compute the hidden
        if (lane < 8) {
            float acc = 0.f;
            const float* ea = edge_attr + (size_t)e * 32;
            #pragma unroll 8
            for (int a = 0; a < 32; ++a) acc += ea[a] * sF1[a * 8 + lane];
            u8[lane] = ssp_f(acc * INVS32f);
        }
        __syncwarp();
        // we -> wbuf
        {
            float a[8] = {0.f,0.f,0.f,0.f,0.f,0.f,0.f,0.f};
            #pragma unroll
            for (int p = 0; p < 8; ++p) {
                float up = u8[p];
                const float* wr = sF2 + p * 256;
                #pragma unroll
                for (int r = 0; r < 8; ++r) a[r] += up * wr[lane + 32 * r];
            }
            #pragma unroll
            for (int r = 0; r < 8; ++r) wbuf[lane + 32 * r] = a[r] * INVS8f;
        }
        // t = silu(s0 @ A1 + a1b)
        {
            float a0 = 0.f, a1 = 0.f;
            #pragma unroll 4
            for (int k = 0; k < 128; ++k) {
                float c = s0[k];
                a0 += c * sA1[k * 64 + lane];
                a1 += c * sA1[k * 64 + lane + 32];
            }
            t[lane]      = silu_f(a0 + sa1b[lane]);
            t[lane + 32] = silu_f(a1 + sa1b[lane + 32]);
        }
        __syncwarp();
        // ws, then w = we * ws  (same-lane wbuf indices: no sync needed)
        {
            float a[8] = {0.f,0.f,0.f,0.f,0.f,0.f,0.f,0.f};
            #pragma unroll 2
            for (int k = 0; k < 64; ++k) {
                float c = t[k];
                const float* wr = sA2 + k * 256;
                #pragma unroll
                for (int r = 0; r < 8; ++r) a[r] += c * wr[lane + 32 * r];
            }
            #pragma unroll
            for (int r = 0; r < 8; ++r) {
                int j = lane + 32 * r;
                wbuf[j] = wbuf[j] * (a[r] + sa2b[j]);
            }
        }
        // gather h (reuse buffers)
        const float* hs = g_h + (size_t)src * 256;
        const float* hd = g_h + (size_t)dst * 256;
        for (int i = lane; i < 256; i += 32) { bufs[i] = hs[i]; bufd[i] = hd[i]; }
        __syncwarp();

        float* outp = g_pair + (size_t)e * 256;
        #pragma unroll
        for (int r = 0; r < 2; ++r) {
            int u = lane + 32 * r;
            float xs = bufs[u], ys = bufd[u];
            float xv0 = bufs[64 + 3 * u + 0], xv1 = bufs[64 + 3 * u + 1], xv2 = bufs[64 + 3 * u + 2];
            float yv0 = bufd[64 + 3 * u + 0], yv1 = bufd[64 + 3 * u + 1], yv2 = bufd[64 + 3 * u + 2];
            float dotv = xv0 * yv0 + xv1 * yv1 + xv2 * yv2;
            outp[u] = CSSf * wbuf[u] * xs * ys + CVVf * wbuf[192 + u] * dotv;
            float wsv = CSVf * wbuf[64 + u] * xs;
            float wvs = CSVf * wbuf[128 + u] * ys;
            outp[64 + 3 * u + 0] = wsv * yv0 + wvs * xv0;
            outp[64 + 3 * u + 1] = wsv * yv1 + wvs * xv1;
            outp[64 + 3 * u + 2] = wsv * yv2 + wvs * xv2;
        }
        __syncwarp();
    }
}

// ======================= kernel 3: edge phase B =======================
// out[e] = e3nn_linear(norm_gate(g_pair[e], ng2), Wr) + node_pair_attr[e]
__global__ void __launch_bounds__(512) edgeB_kernel(
    int E,
    const float* __restrict__ npa,
    const float* __restrict__ W1, const float* __restrict__ b1,
    const float* __restrict__ W2, const float* __restrict__ b2,
    const float* __restrict__ Wr0, const float* __restrict__ Wr1, const float* __restrict__ br0,
    float* __restrict__ out)
{
    extern __shared__ float sh[];
    float* sW1  = sh;             // 16384
    float* sW2  = sh + 16384;     // 16384
    float* sWr0 = sh + 32768;     // 4096
    float* sWr1 = sh + 36864;     // 4096
    float* sb   = sh + 40960;     // 320: [b1 128][b2 128][br0 64]
    float* sstage = sh + 41280;   // 16 * 768

    int tid = threadIdx.x;
    for (int i = tid; i < 16384; i += 512) { sW1[i] = W1[i]; sW2[i] = W2[i]; }
    for (int i = tid; i < 4096; i += 512)  { sWr0[i] = Wr0[i]; sWr1[i] = Wr1[i]; }
    if (tid < 128) { sb[tid] = b1[tid]; sb[128 + tid] = b2[tid]; }
    if (tid < 64)  sb[256 + tid] = br0[tid];
    __syncthreads();
    const float* sb1  = sb;
    const float* sb2  = sb + 128;
    const float* sbr0 = sb + 256;

    int warp = tid >> 5, lane = tid & 31;
    int gw = blockIdx.x * 16 + warp;
    int nwarps = gridDim.x * 16;
    float* st  = sstage + warp * 768;
    float* p   = st;         // 256
    float* cat = st + 256;   // 128
    float* g1  = st + 384;   // 128
    float* gv  = st + 512;   // 128

    for (int e = gw; e < E; e += nwarps) {
        const float* pg = g_pair + (size_t)e * 256;
        for (int i = lane; i < 256; i += 32) p[i] = pg[i];
        __syncwarp();
        #pragma unroll
        for (int r = 0; r < 2; ++r) {
            int u = lane + 32 * r;
            cat[u] = p[u];
            float v0 = p[64 + 3 * u + 0], v1 = p[64 + 3 * u + 1], v2 = p[64 + 3 * u + 2];
            cat[64 + u] = sqrtf(v0 * v0 + v1 * v1 + v2 * v2);
        }
        __syncwarp();
        mv128_warp<true >(sW1, cat, sb1, g1, lane);
        __syncwarp();
        mv128_warp<false>(sW2, g1, sb2, gv, lane);
        __syncwarp();
        // gate v in place; scalar input to final e3nn is gv[0..63]
        #pragma unroll
        for (int r = 0; r < 2; ++r) {
            int u = lane + 32 * r;
            float gu = gv[64 + u];
            p[64 + 3 * u + 0] *= gu;
            p[64 + 3 * u + 1] *= gu;
            p[64 + 3 * u + 2] *= gu;
        }
        __syncwarp();
        // final e3nn + residual add
        const float* np = npa + (size_t)e * 256;
        float* og = out + (size_t)e * 256;
        {
            float a0 = 0.f, a1 = 0.f;
            #pragma unroll 4
            for (int u = 0; u < 64; ++u) {
                float s = gv[u];
                a0 += s * sWr0[u * 64 + lane];
                a1 += s * sWr0[u * 64 + lane + 32];
            }
            og[lane]      = a0 * INV8f + sbr0[lane]      + np[lane];
            og[lane + 32] = a1 * INV8f + sbr0[lane + 32] + np[lane + 32];

            float v00 = 0.f, v01 = 0.f, v02 = 0.f, v10 = 0.f, v11 = 0.f, v12 = 0.f;
            #pragma unroll 4
            for (int u = 0; u < 64; ++u) {
                float w0 = sWr1[u * 64 + lane];
                float w1 = sWr1[u * 64 + lane + 32];
                float e0 = p[64 + 3 * u + 0];
                float e1 = p[64 + 3 * u + 1];
                float e2 = p[64 + 3 * u + 2];
                v00 += e0 * w0; v01 += e1 * w0; v02 += e2 * w0;
                v10 += e0 * w1; v11 += e1 * w1; v12 += e2 * w1;
            }
            int w2 = lane + 32;
            og[64 + 3 * lane + 0] = v00 * INV8f + np[64 + 3 * lane + 0];
            og[64 + 3 * lane + 1] = v01 * INV8f + np[64 + 3 * lane + 1];
            og[64 + 3 * lane + 2] = v02 * INV8f + np[64 + 3 * lane + 2];
            og[64 + 3 * w2 + 0]   = v10 * INV8f + np[64 + 3 * w2 + 0];
            og[64 + 3 * w2 + 1]   = v11 * INV8f + np[64 + 3 * w2 + 1];
            og[64 + 3 * w2 + 2]   = v12 * INV8f + np[64 + 3 * w2 + 2];
        }
        __syncwarp();
    }
}

// ======================= launcher =======================
extern "C" void kernel_launch(void* const* d_in, const int* in_sizes, int n_in,
                              void* d_out, int out_size)
{
    const float* node_attr = (const float*)d_in[0];
    const int*   eidx      = (const int*)  d_in[1];
    const float* edge_attr = (const float*)d_in[2];
    const float* npa       = (const float*)d_in[3];
    const float* Wli0 = (const float*)d_in[4];
    const float* Wli1 = (const float*)d_in[5];
    const float* bli0 = (const float*)d_in[6];
    const float* ng1_W1 = (const float*)d_in[7];
    const float* ng1_b1 = (const float*)d_in[8];
    const float* ng1_W2 = (const float*)d_in[9];
    const float* ng1_b2 = (const float*)d_in[10];
    const float* Wlp0 = (const float*)d_in[11];
    const float* Wlp1 = (const float*)d_in[12];
    const float* blp0 = (const float*)d_in[13];
    const float* Wfc1 = (const float*)d_in[14];
    const float* Wfc2 = (const float*)d_in[15];
    const float* A1   = (const float*)d_in[16];
    const float* a1b  = (const float*)d_in[17];
    const float* A2   = (const float*)d_in[18];
    const float* a2b  = (const float*)d_in[19];
    const float* ng2_W1 = (const float*)d_in[20];
    const float* ng2_b1 = (const float*)d_in[21];
    const float* ng2_W2 = (const float*)d_in[22];
    const float* ng2_b2 = (const float*)d_in[23];
    const float* Wr0  = (const float*)d_in[24];
    const float* Wr1  = (const float*)d_in[25];
    const float* br0  = (const float*)d_in[26];
    float* out = (float*)d_out;

    int N = in_sizes[0] / 256;
    int E = in_sizes[1] / 2;

    size_t shN = (size_t)(49536 + 8 * 1024) * sizeof(float);   // 230912 B
    size_t shA = (size_t)(27200 + 16 * 1024) * sizeof(float);  // 174336 B
    size_t shB = (size_t)(41280 + 16 * 768) * sizeof(float);   // 214272 B

    cudaFuncSetAttribute(node_kernel,  cudaFuncAttributeMaxDynamicSharedMemorySize, (int)shN);
    cudaFuncSetAttribute(edgeA_kernel, cudaFuncAttributeMaxDynamicSharedMemorySize, (int)shA);
    cudaFuncSetAttribute(edgeB_kernel, cudaFuncAttributeMaxDynamicSharedMemorySize, (int)shB);

    node_kernel<<<100, 256, shN>>>(node_attr, N, Wli0, Wli1, bli0,
                                   ng1_W1, ng1_b1, ng1_W2, ng1_b2,
                                   Wlp0, Wlp1, blp0);
    edgeA_kernel<<<148, 512, shA>>>(eidx, E, edge_attr, A1, a1b, A2, a2b, Wfc1, Wfc2);
    edgeB_kernel<<<148, 512, shB>>>(E, npa, ng2_W1, ng2_b1, ng2_W2, ng2_b2,
                                    Wr0, Wr1, br0, out);
}

// round 2
// speedup vs baseline: 1.3592x; 1.3592x over previous
#include <cuda_runtime.h>
#include <cstdint>

// ---------------- constants ----------------
#define LN2f    0.6931471805599453f
#define CSSf    0.7071067811865476f   // 1/sqrt(2)
#define CVVf    0.4082482904638631f   // 1/sqrt(6)
#define CSVf    0.7071067811865476f   // 1/sqrt(2)
#define INV8f   0.125f                // 1/sqrt(64)
#define INVS32f 0.17677669529663687f  // 1/sqrt(32)
#define INVS8f  0.3535533905932738f   // 1/sqrt(8)

#define NMAXN 5000
#define EMAXE 131072

// ---------------- scratch (static device arrays; no allocation) ----------------
__device__ float g_n0[(size_t)NMAXN * 256];
__device__ float g_h [(size_t)NMAXN * 256];
__device__ float g_pair[(size_t)EMAXE * 256];

__device__ __forceinline__ float silu_f(float x) { return x / (1.f + __expf(-x)); }
__device__ __forceinline__ float ssp_f(float x) {
    return fmaxf(x, 0.f) + log1pf(__expf(-fabsf(x))) - LN2f;
}

// warp e3nn_linear: xin = shared 256 merged (s[64] | v[64*3]); writes merged 256 to global
__device__ __forceinline__ void e3nn_warp(const float* __restrict__ xin,
                                          const float* __restrict__ W0s,
                                          const float* __restrict__ W1s,
                                          const float* __restrict__ b0s,
                                          float* __restrict__ outg,
                                          int lane)
{
    float a0 = 0.f, a1 = 0.f;
    #pragma unroll 4
    for (int u = 0; u < 64; ++u) {
        float s = xin[u];
        a0 += s * W0s[u * 64 + lane];
        a1 += s * W0s[u * 64 + lane + 32];
    }
    outg[lane]      = a0 * INV8f + b0s[lane];
    outg[lane + 32] = a1 * INV8f + b0s[lane + 32];

    float v00 = 0.f, v01 = 0.f, v02 = 0.f, v10 = 0.f, v11 = 0.f, v12 = 0.f;
    #pragma unroll 4
    for (int u = 0; u < 64; ++u) {
        float w0 = W1s[u * 64 + lane];
        float w1 = W1s[u * 64 + lane + 32];
        float e0 = xin[64 + 3 * u + 0];
        float e1 = xin[64 + 3 * u + 1];
        float e2 = xin[64 + 3 * u + 2];
        v00 += e0 * w0; v01 += e1 * w0; v02 += e2 * w0;
        v10 += e0 * w1; v11 += e1 * w1; v12 += e2 * w1;
    }
    int w2 = lane + 32;
    outg[64 + 3 * lane + 0] = v00 * INV8f;
    outg[64 + 3 * lane + 1] = v01 * INV8f;
    outg[64 + 3 * lane + 2] = v02 * INV8f;
    outg[64 + 3 * w2 + 0]   = v10 * INV8f;
    outg[64 + 3 * w2 + 1]   = v11 * INV8f;
    outg[64 + 3 * w2 + 2]   = v12 * INV8f;
}

// warp 128->128 matvec from shared weights, optional silu (unbatched, node kernel)
template<bool ACT>
__device__ __forceinline__ void mv128_warp(const float* __restrict__ Ws,
                                           const float* __restrict__ in,
                                           const float* __restrict__ bs,
                                           float* __restrict__ out, int lane)
{
    float a0 = 0.f, a1 = 0.f, a2 = 0.f, a3 = 0.f;
    #pragma unroll 4
    for (int k = 0; k < 128; ++k) {
        float c = in[k];
        const float* wr = Ws + k * 128;
        a0 += c * wr[lane];
        a1 += c * wr[lane + 32];
        a2 += c * wr[lane + 64];
        a3 += c * wr[lane + 96];
    }
    a0 += bs[lane]; a1 += bs[lane + 32]; a2 += bs[lane + 64]; a3 += bs[lane + 96];
    if (ACT) { a0 = silu_f(a0); a1 = silu_f(a1); a2 = silu_f(a2); a3 = silu_f(a3); }
    out[lane] = a0; out[lane + 32] = a1; out[lane + 64] = a2; out[lane + 96] = a3;
}

// ======================= kernel 1: per-node precompute =======================
__global__ void __launch_bounds__(256) node_kernel(
    const float* __restrict__ node_attr, int N,
    const float* __restrict__ Wli0, const float* __restrict__ Wli1, const float* __restrict__ bli0,
    const float* __restrict__ W1, const float* __restrict__ b1,
    const float* __restrict__ W2, const float* __restrict__ b2,
    const float* __restrict__ Wlp0, const float* __restrict__ Wlp1, const float* __restrict__ blp0)
{
    extern __shared__ float sh[];
    float* sWli0 = sh;              // 4096
    float* sWli1 = sh + 4096;       // 4096
    float* sWlp0 = sh + 8192;       // 4096
    float* sWlp1 = sh + 12288;      // 4096
    float* sW1   = sh + 16384;      // 16384
    float* sW2   = sh + 32768;      // 16384
    float* sbias = sh + 49152;      // 384
    float* sstage= sh + 49536;      // 8 * 1024

    int tid = threadIdx.x;
    for (int i = tid; i < 4096; i += 256) {
        sWli0[i] = Wli0[i]; sWli1[i] = Wli1[i];
        sWlp0[i] = Wlp0[i]; sWlp1[i] = Wlp1[i];
    }
    for (int i = tid; i < 16384; i += 256) { sW1[i] = W1[i]; sW2[i] = W2[i]; }
    if (tid < 64)  { sbias[tid] = bli0[tid]; sbias[320 + tid] = blp0[tid]; }
    if (tid < 128) { sbias[64 + tid] = b1[tid]; sbias[192 + tid] = b2[tid]; }
    __syncthreads();

    const float* sbli0 = sbias;
    const float* sb1   = sbias + 64;
    const float* sb2   = sbias + 192;
    const float* sblp0 = sbias + 320;

    int warp = tid >> 5, lane = tid & 31;
    int gw = blockIdx.x * 8 + warp;
    int nwarps = gridDim.x * 8;
    float* st  = sstage + warp * 1024;
    float* x   = st;          // 256
    float* cat = st + 256;    // 128
    float* g1  = st + 384;    // 128
    float* gv  = st + 512;    // 128
    float* hg  = st + 640;    // 256

    for (int node = gw; node < N; node += nwarps) {
        const float* xg = node_attr + (size_t)node * 256;
        for (int i = lane; i < 256; i += 32) x[i] = xg[i];
        __syncwarp();

        e3nn_warp(x, sWli0, sWli1, sbli0, g_n0 + (size_t)node * 256, lane);

        #pragma unroll
        for (int r = 0; r < 2; ++r) {
            int u = lane + 32 * r;
            cat[u] = x[u];
            float v0 = x[64 + 3 * u], v1 = x[64 + 3 * u + 1], v2 = x[64 + 3 * u + 2];
            cat[64 + u] = sqrtf(v0 * v0 + v1 * v1 + v2 * v2);
        }
        __syncwarp();
        mv128_warp<true >(sW1, cat, sb1, g1, lane);
        __syncwarp();
        mv128_warp<false>(sW2, g1, sb2, gv, lane);
        __syncwarp();
        #pragma unroll
        for (int r = 0; r < 2; ++r) {
            int u = lane + 32 * r;
            hg[u] = gv[u];
            float gu = gv[64 + u];
            hg[64 + 3 * u + 0] = x[64 + 3 * u + 0] * gu;
            hg[64 + 3 * u + 1] = x[64 + 3 * u + 1] * gu;
            hg[64 + 3 * u + 2] = x[64 + 3 * u + 2] * gu;
        }
        __syncwarp();
        e3nn_warp(hg, sWlp0, sWlp1, sblp0, g_h + (size_t)node * 256, lane);
        __syncwarp();
    }
}

// ======================= kernel 2: edge phase A (B=4 batched) =======================
__global__ void __launch_bounds__(256) edgeA_kernel(
    const int* __restrict__ eidx, int E,
    const float* __restrict__ edge_attr,
    const float* __restrict__ A1, const float* __restrict__ a1b,
    const float* __restrict__ A2, const float* __restrict__ a2b,
    const float* __restrict__ F1, const float* __restrict__ F2)
{
    extern __shared__ float sh[];
    float* sA1 = sh;             // 8192 (128x64)
    float* sA2 = sh + 8192;      // 16384 (64x256)
    float* sF1 = sh + 24576;     // 256 (32x8)
    float* sF2 = sh + 24832;     // 2048 (8x256)
    float* sb  = sh + 26880;     // 320: [a1b 64][a2b 256]
    float* sstage = sh + 27200;  // 8 * 3072

    int tid = threadIdx.x;
    for (int i = tid; i < 8192; i += 256)  sA1[i] = A1[i];
    for (int i = tid; i < 16384; i += 256) sA2[i] = A2[i];
    if (tid < 256) { sF1[tid] = F1[tid]; sb[64 + tid] = a2b[tid]; }
    for (int i = tid; i < 2048; i += 256)  sF2[i] = F2[i];
    if (tid < 64)  sb[tid] = a1b[tid];
    __syncthreads();
    const float* sa1b = sb;
    const float* sa2b = sb + 64;

    int warp = tid >> 5, lane = tid & 31;
    int gw = blockIdx.x * 8 + warp;
    int nwarps = gridDim.x * 8;
    float* st   = sstage + warp * 3072;
    float* bufd = st;         // 4*256: n0[dst] -> s0 in [b][0..127] -> h[dst]
    float* bufs = st + 1024;  // 4*256: n0[src] -> u8[0..31], t[256..511] -> h[src]
    float* wbuf = st + 2048;  // 4*256

    for (int base = gw * 4; base < E; base += nwarps * 4) {
        int eb[4], dstv[4], srcv[4];
        #pragma unroll
        for (int b = 0; b < 4; ++b) {
            eb[b]   = min(base + b, E - 1);
            dstv[b] = eidx[eb[b]];
            srcv[b] = eidx[E + eb[b]];
        }
        // gather n0
        for (int i = lane; i < 256; i += 32) {
            #pragma unroll
            for (int b = 0; b < 4; ++b) {
                bufd[b * 256 + i] = g_n0[(size_t)dstv[b] * 256 + i];
                bufs[b * 256 + i] = g_n0[(size_t)srcv[b] * 256 + i];
            }
        }
        __syncwarp();

        // s0 into registers
        float rs[4][2], rip[4][2];
        #pragma unroll
        for (int r = 0; r < 2; ++r) {
            int u = lane + 32 * r;
            #pragma unroll
            for (int b = 0; b < 4; ++b) {
                const float* bd = bufd + b * 256;
                const float* bs = bufs + b * 256;
                rs[b][r]  = 0.5f * (bd[u] + bs[u]);
                rip[b][r] = (bd[64 + 3 * u + 0] * bs[64 + 3 * u + 0]
                           + bd[64 + 3 * u + 1] * bs[64 + 3 * u + 1]
                           + bd[64 + 3 * u + 2] * bs[64 + 3 * u + 2]) * (1.f / 3.f);
            }
        }
        __syncwarp();   // WAR: all reads done before overwrite
        #pragma unroll
        for (int r = 0; r < 2; ++r) {
            int u = lane + 32 * r;
            #pragma unroll
            for (int b = 0; b < 4; ++b) {
                bufd[b * 256 + u]      = rs[b][r];
                bufd[b * 256 + 64 + u] = rip[b][r];
            }
        }
        // u8: lane -> (b = lane>>3, j = lane&7)
        {
            int b = lane >> 3, j = lane & 7;
            const float* ea = edge_attr + (size_t)eb[b] * 32;
            float acc = 0.f;
            #pragma unroll 8
            for (int a = 0; a < 32; ++a) acc += ea[a] * sF1[a * 8 + j];
            bufs[b * 8 + j] = ssp_f(acc * INVS32f);
        }
        __syncwarp();

        // we -> wbuf (serial over b; F2 small)
        #pragma unroll
        for (int b = 0; b < 4; ++b) {
            float a[8] = {0.f,0.f,0.f,0.f,0.f,0.f,0.f,0.f};
            #pragma unroll
            for (int p = 0; p < 8; ++p) {
                float up = bufs[b * 8 + p];
                const float* wr = sF2 + p * 256;
                #pragma unroll
                for (int r = 0; r < 8; ++r) a[r] += up * wr[lane + 32 * r];
            }
            #pragma unroll
            for (int r = 0; r < 8; ++r) wbuf[b * 256 + lane + 32 * r] = a[r] * INVS8f;
        }
        // t = silu(s0 @ A1 + a1b), batched
        {
            float a0[4] = {0.f,0.f,0.f,0.f}, a1[4] = {0.f,0.f,0.f,0.f};
            #pragma unroll 4
            for (int k = 0; k < 128; ++k) {
                float w0 = sA1[k * 64 + lane];
                float w1 = sA1[k * 64 + lane + 32];
                #pragma unroll
                for (int b = 0; b < 4; ++b) {
                    float c = bufd[b * 256 + k];
                    a0[b] += c * w0;
                    a1[b] += c * w1;
                }
            }
            #pragma unroll
            for (int b = 0; b < 4; ++b) {
                bufs[256 + b * 64 + lane]      = silu_f(a0[b] + sa1b[lane]);
                bufs[256 + b * 64 + lane + 32] = silu_f(a1[b] + sa1b[lane + 32]);
            }
        }
        __syncwarp();
        // ws batched, then w = we * ws (wbuf same-lane RMW)
        {
            float acc[4][8];
            #pragma unroll
            for (int b = 0; b < 4; ++b)
                #pragma unroll
                for (int r = 0; r < 8; ++r) acc[b][r] = 0.f;
            #pragma unroll 2
            for (int k = 0; k < 64; ++k) {
                float w[8];
                const float* wr = sA2 + k * 256;
                #pragma unroll
                for (int r = 0; r < 8; ++r) w[r] = wr[lane + 32 * r];
                #pragma unroll
                for (int b = 0; b < 4; ++b) {
                    float c = bufs[256 + b * 64 + k];
                    #pragma unroll
                    for (int r = 0; r < 8; ++r) acc[b][r] += c * w[r];
                }
            }
            #pragma unroll
            for (int b = 0; b < 4; ++b)
                #pragma unroll
                for (int r = 0; r < 8; ++r) {
                    int j = lane + 32 * r;
                    wbuf[b * 256 + j] *= (acc[b][r] + sa2b[j]);
                }
        }
        __syncwarp();   // t region read complete before h-gather overwrites
        // gather h
        for (int i = lane; i < 256; i += 32) {
            #pragma unroll
            for (int b = 0; b < 4; ++b) {
                bufs[b * 256 + i] = g_h[(size_t)srcv[b] * 256 + i];
                bufd[b * 256 + i] = g_h[(size_t)dstv[b] * 256 + i];
            }
        }
        __syncwarp();

        // tensor product + write g_pair
        #pragma unroll
        for (int r = 0; r < 2; ++r) {
            int u = lane + 32 * r;
            #pragma unroll
            for (int b = 0; b < 4; ++b) {
                if (base + b >= E) continue;
                const float* xb = bufs + b * 256;
                const float* yb = bufd + b * 256;
                const float* wb = wbuf + b * 256;
                float xs = xb[u], ys = yb[u];
                float xv0 = xb[64 + 3 * u + 0], xv1 = xb[64 + 3 * u + 1], xv2 = xb[64 + 3 * u + 2];
                float yv0 = yb[64 + 3 * u + 0], yv1 = yb[64 + 3 * u + 1], yv2 = yb[64 + 3 * u + 2];
                float dotv = xv0 * yv0 + xv1 * yv1 + xv2 * yv2;
                float* outp = g_pair + (size_t)(base + b) * 256;
                outp[u] = CSSf * wb[u] * xs * ys + CVVf * wb[192 + u] * dotv;
                float wsv = CSVf * wb[64 + u] * xs;
                float wvs = CSVf * wb[128 + u] * ys;
                outp[64 + 3 * u + 0] = wsv * yv0 + wvs * xv0;
                outp[64 + 3 * u + 1] = wsv * yv1 + wvs * xv1;
                outp[64 + 3 * u + 2] = wsv * yv2 + wvs * xv2;
            }
        }
        __syncwarp();
    }
}

// ======================= kernel 3: edge phase B (B=4 batched) =======================
__global__ void __launch_bounds__(256) edgeB_kernel(
    int E,
    const float* __restrict__ npa,
    const float* __restrict__ W1, const float* __restrict__ b1,
    const float* __restrict__ W2, const float* __restrict__ b2,
    const float* __restrict__ Wr0, const float* __restrict__ Wr1, const float* __restrict__ br0,
    float* __restrict__ out)
{
    extern __shared__ float sh[];
    float* sW1  = sh;             // 16384
    float* sW2  = sh + 16384;     // 16384
    float* sWr0 = sh + 32768;     // 4096
    float* sWr1 = sh + 36864;     // 4096
    float* sb   = sh + 40960;     // 320
    float* sstage = sh + 41280;   // 8 * 2048

    int tid = threadIdx.x;
    for (int i = tid; i < 16384; i += 256) { sW1[i] = W1[i]; sW2[i] = W2[i]; }
    for (int i = tid; i < 4096; i += 256)  { sWr0[i] = Wr0[i]; sWr1[i] = Wr1[i]; }
    if (tid < 128) { sb[tid] = b1[tid]; sb[128 + tid] = b2[tid]; }
    if (tid < 64)  sb[256 + tid] = br0[tid];
    __syncthreads();
    const float* sb1  = sb;
    const float* sb2  = sb + 128;
    const float* sbr0 = sb + 256;

    int warp = tid >> 5, lane = tid & 31;
    int gw = blockIdx.x * 8 + warp;
    int nwarps = gridDim.x * 8;
    float* st  = sstage + warp * 2048;
    float* p   = st;          // 4*256
    float* cat = st + 1024;   // 4*128 (later: gv)
    float* g1  = st + 1536;   // 4*128

    for (int base = gw * 4; base < E; base += nwarps * 4) {
        // load p
        for (int i = lane; i < 256; i += 32) {
            #pragma unroll
            for (int b = 0; b < 4; ++b) {
                int e = min(base + b, E - 1);
                p[b * 256 + i] = g_pair[(size_t)e * 256 + i];
            }
        }
        __syncwarp();
        // cat = [s, |v|]
        #pragma unroll
        for (int r = 0; r < 2; ++r) {
            int u = lane + 32 * r;
            #pragma unroll
            for (int b = 0; b < 4; ++b) {
                const float* pb = p + b * 256;
                cat[b * 128 + u] = pb[u];
                float v0 = pb[64 + 3 * u + 0], v1 = pb[64 + 3 * u + 1], v2 = pb[64 + 3 * u + 2];
                cat[b * 128 + 64 + u] = sqrtf(v0 * v0 + v1 * v1 + v2 * v2);
            }
        }
        __syncwarp();
        // g1 = silu(cat @ W1 + b1), batched
        {
            float a[4][4];
            #pragma unroll
            for (int b = 0; b < 4; ++b)
                #pragma unroll
                for (int r = 0; r < 4; ++r) a[b][r] = 0.f;
            #pragma unroll 2
            for (int k = 0; k < 128; ++k) {
                const float* wr = sW1 + k * 128;
                float w0 = wr[lane], w1 = wr[lane + 32], w2 = wr[lane + 64], w3 = wr[lane + 96];
                #pragma unroll
                for (int b = 0; b < 4; ++b) {
                    float c = cat[b * 128 + k];
                    a[b][0] += c * w0; a[b][1] += c * w1;
                    a[b][2] += c * w2; a[b][3] += c * w3;
                }
            }
            #pragma unroll
            for (int b = 0; b < 4; ++b)
                #pragma unroll
                for (int r = 0; r < 4; ++r) {
                    int j = lane + 32 * r;
                    g1[b * 128 + j] = silu_f(a[b][r] + sb1[j]);
                }
        }
        __syncwarp();
        // gv = g1 @ W2 + b2 -> overwrite cat
        {
            float a[4][4];
            #pragma unroll
            for (int b = 0; b < 4; ++b)
                #pragma unroll
                for (int r = 0; r < 4; ++r) a[b][r] = 0.f;
            #pragma unroll 2
            for (int k = 0; k < 128; ++k) {
                const float* wr = sW2 + k * 128;
                float w0 = wr[lane], w1 = wr[lane + 32], w2 = wr[lane + 64], w3 = wr[lane + 96];
                #pragma unroll
                for (int b = 0; b < 4; ++b) {
                    float c = g1[b * 128 + k];
                    a[b][0] += c * w0; a[b][1] += c * w1;
                    a[b][2] += c * w2; a[b][3] += c * w3;
                }
            }
            __syncwarp();  // all g1 reads done AND all cat reads (from W1 stage) done
            #pragma unroll
            for (int b = 0; b < 4; ++b)
                #pragma unroll
                for (int r = 0; r < 4; ++r) {
                    int j = lane + 32 * r;
                    cat[b * 128 + j] = a[b][r] + sb2[j];
                }
        }
        // gate p vector parts in place (same-lane gv reads)
        #pragma unroll
        for (int r = 0; r < 2; ++r) {
            int u = lane + 32 * r;
            #pragma unroll
            for (int b = 0; b < 4; ++b) {
                float gu = cat[b * 128 + 64 + u];
                p[b * 256 + 64 + 3 * u + 0] *= gu;
                p[b * 256 + 64 + 3 * u + 1] *= gu;
                p[b * 256 + 64 + 3 * u + 2] *= gu;
            }
        }
        __syncwarp();
        // final e3nn + residual, batched
        {
            // scalar part: gv scalars are cat[b*128 + 0..63]
            float a0[4] = {0.f,0.f,0.f,0.f}, a1[4] = {0.f,0.f,0.f,0.f};
            #pragma unroll 4
            for (int u = 0; u < 64; ++u) {
                float w0 = sWr0[u * 64 + lane];
                float w1 = sWr0[u * 64 + lane + 32];
                #pragma unroll
                for (int b = 0; b < 4; ++b) {
                    float c = cat[b * 128 + u];
                    a0[b] += c * w0;
                    a1[b] += c * w1;
                }
            }
            #pragma unroll
            for (int b = 0; b < 4; ++b) {
                if (base + b >= E) continue;
                const float* np = npa + (size_t)(base + b) * 256;
                float* og = out + (size_t)(base + b) * 256;
                og[lane]      = a0[b] * INV8f + sbr0[lane]      + np[lane];
                og[lane + 32] = a1[b] * INV8f + sbr0[lane + 32] + np[lane + 32];
            }
            // vector part
            float v[4][6];
            #pragma unroll
            for (int b = 0; b < 4; ++b)
                #pragma unroll
                for (int r = 0; r < 6; ++r) v[b][r] = 0.f;
            #pragma unroll 2
            for (int u = 0; u < 64; ++u) {
                float w0 = sWr1[u * 64 + lane];
                float w1 = sWr1[u * 64 + lane + 32];
                #pragma unroll
                for (int b = 0; b < 4; ++b) {
                    const float* pb = p + b * 256;
                    float e0 = pb[64 + 3 * u + 0];
                    float e1 = pb[64 + 3 * u + 1];
                    float e2 = pb[64 + 3 * u + 2];
                    v[b][0] += e0 * w0; v[b][1] += e1 * w0; v[b][2] += e2 * w0;
                    v[b][3] += e0 * w1; v[b][4] += e1 * w1; v[b][5] += e2 * w1;
                }
            }
            int w2l = lane + 32;
            #pragma unroll
            for (int b = 0; b < 4; ++b) {
                if (base + b >= E) continue;
                const float* np = npa + (size_t)(base + b) * 256;
                float* og = out + (size_t)(base + b) * 256;
                og[64 + 3 * lane + 0] = v[b][0] * INV8f + np[64 + 3 * lane + 0];
                og[64 + 3 * lane + 1] = v[b][1] * INV8f + np[64 + 3 * lane + 1];
                og[64 + 3 * lane + 2] = v[b][2] * INV8f + np[64 + 3 * lane + 2];
                og[64 + 3 * w2l + 0]  = v[b][3] * INV8f + np[64 + 3 * w2l + 0];
                og[64 + 3 * w2l + 1]  = v[b][4] * INV8f + np[64 + 3 * w2l + 1];
                og[64 + 3 * w2l + 2]  = v[b][5] * INV8f + np[64 + 3 * w2l + 2];
            }
        }
        __syncwarp();
    }
}

// ======================= launcher =======================
extern "C" void kernel_launch(void* const* d_in, const int* in_sizes, int n_in,
                              void* d_out, int out_size)
{
    const float* node_attr = (const float*)d_in[0];
    const int*   eidx      = (const int*)  d_in[1];
    const float* edge_attr = (const float*)d_in[2];
    const float* npa       = (const float*)d_in[3];
    const float* Wli0 = (const float*)d_in[4];
    const float* Wli1 = (const float*)d_in[5];
    const float* bli0 = (const float*)d_in[6];
    const float* ng1_W1 = (const float*)d_in[7];
    const float* ng1_b1 = (const float*)d_in[8];
    const float* ng1_W2 = (const float*)d_in[9];
    const float* ng1_b2 = (const float*)d_in[10];
    const float* Wlp0 = (const float*)d_in[11];
    const float* Wlp1 = (const float*)d_in[12];
    const float* blp0 = (const float*)d_in[13];
    const float* Wfc1 = (const float*)d_in[14];
    const float* Wfc2 = (const float*)d_in[15];
    const float* A1   = (const float*)d_in[16];
    const float* a1b  = (const float*)d_in[17];
    const float* A2   = (const float*)d_in[18];
    const float* a2b  = (const float*)d_in[19];
    const float* ng2_W1 = (const float*)d_in[20];
    const float* ng2_b1 = (const float*)d_in[21];
    const float* ng2_W2 = (const float*)d_in[22];
    const float* ng2_b2 = (const float*)d_in[23];
    const float* Wr0  = (const float*)d_in[24];
    const float* Wr1  = (const float*)d_in[25];
    const float* br0  = (const float*)d_in[26];
    float* out = (float*)d_out;

    int N = in_sizes[0] / 256;
    int E = in_sizes[1] / 2;

    size_t shN = (size_t)(49536 + 8 * 1024) * sizeof(float);   // 230912 B
    size_t shA = (size_t)(27200 + 8 * 3072) * sizeof(float);   // 207104 B
    size_t shB = (size_t)(41280 + 8 * 2048) * sizeof(float);   // 230656 B

    cudaFuncSetAttribute(node_kernel,  cudaFuncAttributeMaxDynamicSharedMemorySize, (int)shN);
    cudaFuncSetAttribute(edgeA_kernel, cudaFuncAttributeMaxDynamicSharedMemorySize, (int)shA);
    cudaFuncSetAttribute(edgeB_kernel, cudaFuncAttributeMaxDynamicSharedMemorySize, (int)shB);

    node_kernel<<<148, 256, shN>>>(node_attr, N, Wli0, Wli1, bli0,
                                   ng1_W1, ng1_b1, ng1_W2, ng1_b2,
                                   Wlp0, Wlp1, blp0);
    edgeA_kernel<<<148, 256, shA>>>(eidx, E, edge_attr, A1, a1b, A2, a2b, Wfc1, Wfc2);
    edgeB_kernel<<<148, 256, shB>>>(E, npa, ng2_W1, ng2_b1, ng2_W2, ng2_b2,
                                    Wr0, Wr1, br0, out);
}

// round 4
// speedup vs baseline: 1.5828x; 1.1645x over previous
#include <cuda_runtime.h>
#include <cstdint>

// ---------------- constants ----------------
#define LN2f    0.6931471805599453f
#define CSSf    0.7071067811865476f   // 1/sqrt(2)
#define CVVf    0.4082482904638631f   // 1/sqrt(6)
#define CSVf    0.7071067811865476f   // 1/sqrt(2)
#define INV8f   0.125f                // 1/sqrt(64)
#define INVS32f 0.17677669529663687f  // 1/sqrt(32)
#define INVS8f  0.3535533905932738f   // 1/sqrt(8)

#define NMAXN 5000
#define EMAXE 131072

__device__ float g_n0[(size_t)NMAXN * 256];
__device__ float g_h [(size_t)NMAXN * 256];
__device__ float g_pair[(size_t)EMAXE * 256];

__device__ __forceinline__ float silu_f(float x) { return x / (1.f + __expf(-x)); }
__device__ __forceinline__ float ssp_f(float x) {
    return fmaxf(x, 0.f) + log1pf(__expf(-fabsf(x))) - LN2f;
}
__device__ __forceinline__ const float4* c4(const float* p) { return (const float4*)p; }
__device__ __forceinline__ float4*       m4(float* p)       { return (float4*)p; }
__device__ __forceinline__ const float2* c2(const float* p) { return (const float2*)p; }
__device__ __forceinline__ float2*       m2(float* p)       { return (float2*)p; }

// ---------- vectorized e3nn linear (unbatched; node kernel) ----------
// out cols j = 2*lane, 2*lane+1. xin shared 256 merged; writes canonical to global.
__device__ __forceinline__ void e3nn_v2(const float* __restrict__ xin,
                                        const float* __restrict__ W0s,
                                        const float* __restrict__ W1s,
                                        const float* __restrict__ b0s,
                                        float* __restrict__ outg, int lane)
{
    int j = 2 * lane;
    float ax = 0.f, ay = 0.f;
    #pragma unroll 8
    for (int u2 = 0; u2 < 32; ++u2) {
        float2 c  = *c2(xin + 2 * u2);
        float2 w0 = *c2(W0s + (2 * u2) * 64 + j);
        float2 w1 = *c2(W0s + (2 * u2 + 1) * 64 + j);
        ax += c.x * w0.x + c.y * w1.x;
        ay += c.x * w0.y + c.y * w1.y;
    }
    float2 bb = *c2(b0s + j);
    float2 os = { ax * INV8f + bb.x, ay * INV8f + bb.y };
    *m2(outg + j) = os;

    float v00=0.f,v01=0.f,v02=0.f,v10=0.f,v11=0.f,v12=0.f;
    #pragma unroll 8
    for (int u2 = 0; u2 < 32; ++u2) {
        const float* e = xin + 64 + 6 * u2;
        float2 e01 = *c2(e), e23 = *c2(e + 2), e45 = *c2(e + 4);
        float2 w0 = *c2(W1s + (2 * u2) * 64 + j);
        float2 w1 = *c2(W1s + (2 * u2 + 1) * 64 + j);
        v00 += e01.x * w0.x + e23.y * w1.x;
        v01 += e01.y * w0.x + e45.x * w1.x;
        v02 += e23.x * w0.x + e45.y * w1.x;
        v10 += e01.x * w0.y + e23.y * w1.y;
        v11 += e01.y * w0.y + e45.x * w1.y;
        v12 += e23.x * w0.y + e45.y * w1.y;
    }
    float* o = outg + 64 + 6 * lane;
    float2 o0 = { v00 * INV8f, v01 * INV8f };
    float2 o1 = { v02 * INV8f, v10 * INV8f };
    float2 o2 = { v11 * INV8f, v12 * INV8f };
    *m2(o) = o0; *m2(o + 2) = o1; *m2(o + 4) = o2;
}

// ---------- vectorized 128->128 matvec, unbatched (node kernel) ----------
template<bool ACT>
__device__ __forceinline__ void mv128_v2(const float* __restrict__ Ws,
                                         const float* __restrict__ in,
                                         const float* __restrict__ bs,
                                         float* __restrict__ out, int lane)
{
    int j = 4 * lane;
    float4 a = {0.f,0.f,0.f,0.f};
    #pragma unroll 4
    for (int k4 = 0; k4 < 32; ++k4) {
        float4 c  = *c4(in + 4 * k4);
        float4 w0 = *c4(Ws + (4 * k4 + 0) * 128 + j);
        float4 w1 = *c4(Ws + (4 * k4 + 1) * 128 + j);
        float4 w2 = *c4(Ws + (4 * k4 + 2) * 128 + j);
        float4 w3 = *c4(Ws + (4 * k4 + 3) * 128 + j);
        a.x += c.x*w0.x + c.y*w1.x + c.z*w2.x + c.w*w3.x;
        a.y += c.x*w0.y + c.y*w1.y + c.z*w2.y + c.w*w3.y;
        a.z += c.x*w0.z + c.y*w1.z + c.z*w2.z + c.w*w3.z;
        a.w += c.x*w0.w + c.y*w1.w + c.z*w2.w + c.w*w3.w;
    }
    float4 b = *c4(bs + j);
    a.x += b.x; a.y += b.y; a.z += b.z; a.w += b.w;
    if (ACT) { a.x = silu_f(a.x); a.y = silu_f(a.y); a.z = silu_f(a.z); a.w = silu_f(a.w); }
    *m4(out + j) = a;
}

// ======================= kernel 1: per-node precompute =======================
__global__ void __launch_bounds__(256) node_kernel(
    const float* __restrict__ node_attr, int N,
    const float* __restrict__ Wli0, const float* __restrict__ Wli1, const float* __restrict__ bli0,
    const float* __restrict__ W1, const float* __restrict__ b1,
    const float* __restrict__ W2, const float* __restrict__ b2,
    const float* __restrict__ Wlp0, const float* __restrict__ Wlp1, const float* __restrict__ blp0)
{
    extern __shared__ float sh[];
    float* sWli0 = sh;              // 4096
    float* sWli1 = sh + 4096;
    float* sWlp0 = sh + 8192;
    float* sWlp1 = sh + 12288;
    float* sW1   = sh + 16384;      // 16384
    float* sW2   = sh + 32768;
    float* sbias = sh + 49152;      // 384
    float* sstage= sh + 49536;      // 8 * 1024

    int tid = threadIdx.x;
    for (int i = tid; i < 4096; i += 256) {
        sWli0[i] = Wli0[i]; sWli1[i] = Wli1[i];
        sWlp0[i] = Wlp0[i]; sWlp1[i] = Wlp1[i];
    }
    for (int i = tid; i < 16384; i += 256) { sW1[i] = W1[i]; sW2[i] = W2[i]; }
    if (tid < 64)  { sbias[tid] = bli0[tid]; sbias[320 + tid] = blp0[tid]; }
    if (tid < 128) { sbias[64 + tid] = b1[tid]; sbias[192 + tid] = b2[tid]; }
    __syncthreads();

    const float* sbli0 = sbias;
    const float* sb1   = sbias + 64;
    const float* sb2   = sbias + 192;
    const float* sblp0 = sbias + 320;

    int warp = tid >> 5, lane = tid & 31;
    int gw = blockIdx.x * 8 + warp;
    int nwarps = gridDim.x * 8;
    float* st  = sstage + warp * 1024;
    float* x   = st;          // 256
    float* cat = st + 256;    // 128
    float* g1  = st + 384;    // 128
    float* gv  = st + 512;    // 128
    float* hg  = st + 640;    // 256

    for (int node = gw; node < N; node += nwarps) {
        const float4* xg = c4(node_attr + (size_t)node * 256);
        m4(x)[lane] = xg[lane];
        m4(x)[lane + 32] = xg[lane + 32];
        __syncwarp();

        e3nn_v2(x, sWli0, sWli1, sbli0, g_n0 + (size_t)node * 256, lane);

        {
            float2 s = *c2(x + 2 * lane);
            *m2(cat + 2 * lane) = s;
            const float* e = x + 64 + 6 * lane;
            float2 e01 = *c2(e), e23 = *c2(e + 2), e45 = *c2(e + 4);
            float2 nn = { sqrtf(e01.x*e01.x + e01.y*e01.y + e23.x*e23.x),
                          sqrtf(e23.y*e23.y + e45.x*e45.x + e45.y*e45.y) };
            *m2(cat + 64 + 2 * lane) = nn;
        }
        __syncwarp();
        mv128_v2<true >(sW1, cat, sb1, g1, lane);
        __syncwarp();
        mv128_v2<false>(sW2, g1, sb2, gv, lane);
        __syncwarp();
        {
            float2 s = *c2(gv + 2 * lane);
            *m2(hg + 2 * lane) = s;
            float2 g = *c2(gv + 64 + 2 * lane);
            const float* e = x + 64 + 6 * lane;
            float2 e01 = *c2(e), e23 = *c2(e + 2), e45 = *c2(e + 4);
            float2 o0 = { e01.x * g.x, e01.y * g.x };
            float2 o1 = { e23.x * g.x, e23.y * g.y };
            float2 o2 = { e45.x * g.y, e45.y * g.y };
            float* o = hg + 64 + 6 * lane;
            *m2(o) = o0; *m2(o + 2) = o1; *m2(o + 4) = o2;
        }
        __syncwarp();
        e3nn_v2(hg, sWlp0, sWlp1, sblp0, g_h + (size_t)node * 256, lane);
        __syncwarp();
    }
}

// ======================= kernel 2: edge phase A (B=4, vectorized) =======================
__global__ void __launch_bounds__(256) edgeA_kernel(
    const int* __restrict__ eidx, int E,
    const float* __restrict__ edge_attr,
    const float* __restrict__ A1, const float* __restrict__ a1b,
    const float* __restrict__ A2, const float* __restrict__ a2b,
    const float* __restrict__ F1, const float* __restrict__ F2)
{
    extern __shared__ float sh[];
    float* sA1 = sh;             // 8192 (128x64)
    float* sA2 = sh + 8192;      // 16384 (64x256)
    float* sF1 = sh + 24576;     // 256 (32x8)
    float* sF2 = sh + 24832;     // 2048 (8x256)
    float* sb  = sh + 26880;     // 320: [a1b 64][a2b 256]
    float* sstage = sh + 27200;  // 8 * 3072

    int tid = threadIdx.x;
    for (int i = tid; i < 8192; i += 256)  sA1[i] = A1[i];
    for (int i = tid; i < 16384; i += 256) sA2[i] = A2[i];
    if (tid < 256) { sF1[tid] = F1[tid]; sb[64 + tid] = a2b[tid]; }
    for (int i = tid; i < 2048; i += 256)  sF2[i] = F2[i];
    if (tid < 64)  sb[tid] = a1b[tid];
    __syncthreads();
    const float* sa1b = sb;
    const float* sa2b = sb + 64;

    int warp = tid >> 5, lane = tid & 31;
    int gw = blockIdx.x * 8 + warp;
    int nwarps = gridDim.x * 8;
    float* st   = sstage + warp * 3072;
    float* bufd = st;         // 4*256
    float* bufs = st + 1024;  // 4*256
    float* wbuf = st + 2048;  // 4*256

    for (int base = gw * 4; base < E; base += nwarps * 4) {
        int eb[4], dstv[4], srcv[4];
        #pragma unroll
        for (int b = 0; b < 4; ++b) {
            eb[b]   = min(base + b, E - 1);
            dstv[b] = eidx[eb[b]];
            srcv[b] = eidx[E + eb[b]];
        }
        // gather n0 (float4)
        #pragma unroll
        for (int b = 0; b < 4; ++b) {
            const float4* nd = c4(g_n0 + (size_t)dstv[b] * 256);
            const float4* ns = c4(g_n0 + (size_t)srcv[b] * 256);
            m4(bufd + b * 256)[lane]      = nd[lane];
            m4(bufd + b * 256)[lane + 32] = nd[lane + 32];
            m4(bufs + b * 256)[lane]      = ns[lane];
            m4(bufs + b * 256)[lane + 32] = ns[lane + 32];
        }
        __syncwarp();

        // s0 into registers (u = 2*lane, 2*lane+1)
        float2 rs[4], rip[4];
        #pragma unroll
        for (int b = 0; b < 4; ++b) {
            const float* bd = bufd + b * 256;
            const float* bs = bufs + b * 256;
            float2 sd = *c2(bd + 2 * lane), ss = *c2(bs + 2 * lane);
            rs[b].x = 0.5f * (sd.x + ss.x);
            rs[b].y = 0.5f * (sd.y + ss.y);
            const float* ed = bd + 64 + 6 * lane;
            const float* es = bs + 64 + 6 * lane;
            float2 d01 = *c2(ed), d23 = *c2(ed + 2), d45 = *c2(ed + 4);
            float2 s01 = *c2(es), s23 = *c2(es + 2), s45 = *c2(es + 4);
            rip[b].x = (d01.x*s01.x + d01.y*s01.y + d23.x*s23.x) * (1.f/3.f);
            rip[b].y = (d23.y*s23.y + d45.x*s45.x + d45.y*s45.y) * (1.f/3.f);
        }
        __syncwarp();   // reads done before overwrite
        #pragma unroll
        for (int b = 0; b < 4; ++b) {
            *m2(bufd + b * 256 + 2 * lane) = rs[b];
            *m2(bufd + b * 256 + 64 + 2 * lane) = rip[b];
        }
        // stage edge_attr rows into wbuf[0..127] (float4: lane -> row lane>>3, cols (lane&7)*4)
        {
            int br = lane >> 3, cc = (lane & 7) * 4;
            float4 v = *c4(edge_attr + (size_t)eb[br] * 32 + cc);
            *m4(wbuf + br * 32 + cc) = v;
        }
        __syncwarp();
        // u8 -> bufs[0..31]
        {
            int b = lane >> 3, j = lane & 7;
            float acc = 0.f;
            #pragma unroll 8
            for (int a = 0; a < 32; ++a) acc += wbuf[b * 32 + a] * sF1[a * 8 + j];
            bufs[b * 8 + j] = ssp_f(acc * INVS32f);
        }
        __syncwarp();
        // we -> wbuf (mapping j = 8*lane + r)
        #pragma unroll
        for (int b = 0; b < 4; ++b) {
            float4 a0 = {0,0,0,0}, a1 = {0,0,0,0};
            #pragma unroll
            for (int p = 0; p < 8; ++p) {
                float up = bufs[b * 8 + p];
                float4 w0 = *c4(sF2 + p * 256 + 8 * lane);
                float4 w1 = *c4(sF2 + p * 256 + 8 * lane + 4);
                a0.x += up*w0.x; a0.y += up*w0.y; a0.z += up*w0.z; a0.w += up*w0.w;
                a1.x += up*w1.x; a1.y += up*w1.y; a1.z += up*w1.z; a1.w += up*w1.w;
            }
            a0.x *= INVS8f; a0.y *= INVS8f; a0.z *= INVS8f; a0.w *= INVS8f;
            a1.x *= INVS8f; a1.y *= INVS8f; a1.z *= INVS8f; a1.w *= INVS8f;
            *m4(wbuf + b * 256 + 8 * lane) = a0;
            *m4(wbuf + b * 256 + 8 * lane + 4) = a1;
        }
        // t = silu(s0 @ A1 + a1b)  (mapping j = 2*lane + r)
        {
            float tx[4] = {0,0,0,0}, ty[4] = {0,0,0,0};
            int j = 2 * lane;
            #pragma unroll 2
            for (int k4 = 0; k4 < 32; ++k4) {
                float2 w0 = *c2(sA1 + (4*k4+0) * 64 + j);
                float2 w1 = *c2(sA1 + (4*k4+1) * 64 + j);
                float2 w2 = *c2(sA1 + (4*k4+2) * 64 + j);
                float2 w3 = *c2(sA1 + (4*k4+3) * 64 + j);
                #pragma unroll
                for (int b = 0; b < 4; ++b) {
                    float4 c = *c4(bufd + b * 256 + 4 * k4);
                    tx[b] += c.x*w0.x + c.y*w1.x + c.z*w2.x + c.w*w3.x;
                    ty[b] += c.x*w0.y + c.y*w1.y + c.z*w2.y + c.w*w3.y;
                }
            }
            float2 bb = *c2(sa1b + j);
            #pragma unroll
            for (int b = 0; b < 4; ++b) {
                float2 t2 = { silu_f(tx[b] + bb.x), silu_f(ty[b] + bb.y) };
                *m2(bufs + 256 + b * 64 + j) = t2;
            }
        }
        __syncwarp();
        // ws, then w = we * ws  (same-lane RMW at j = 8*lane + r)
        {
            float4 acc0[4], acc1[4];
            #pragma unroll
            for (int b = 0; b < 4; ++b) { acc0[b] = make_float4(0,0,0,0); acc1[b] = make_float4(0,0,0,0); }
            #pragma unroll 2
            for (int k4 = 0; k4 < 16; ++k4) {
                float4 cc[4];
                #pragma unroll
                for (int b = 0; b < 4; ++b) cc[b] = *c4(bufs + 256 + b * 64 + 4 * k4);
                #pragma unroll
                for (int kk = 0; kk < 4; ++kk) {
                    int k = 4 * k4 + kk;
                    float4 w0 = *c4(sA2 + k * 256 + 8 * lane);
                    float4 w1 = *c4(sA2 + k * 256 + 8 * lane + 4);
                    #pragma unroll
                    for (int b = 0; b < 4; ++b) {
                        float c = (kk == 0) ? cc[b].x : (kk == 1) ? cc[b].y : (kk == 2) ? cc[b].z : cc[b].w;
                        acc0[b].x += c*w0.x; acc0[b].y += c*w0.y; acc0[b].z += c*w0.z; acc0[b].w += c*w0.w;
                        acc1[b].x += c*w1.x; acc1[b].y += c*w1.y; acc1[b].z += c*w1.z; acc1[b].w += c*w1.w;
                    }
                }
            }
            float4 b0 = *c4(sa2b + 8 * lane);
            float4 b1 = *c4(sa2b + 8 * lane + 4);
            #pragma unroll
            for (int b = 0; b < 4; ++b) {
                float4 e0 = *c4(wbuf + b * 256 + 8 * lane);
                float4 e1 = *c4(wbuf + b * 256 + 8 * lane + 4);
                e0.x *= acc0[b].x + b0.x; e0.y *= acc0[b].y + b0.y;
                e0.z *= acc0[b].z + b0.z; e0.w *= acc0[b].w + b0.w;
                e1.x *= acc1[b].x + b1.x; e1.y *= acc1[b].y + b1.y;
                e1.z *= acc1[b].z + b1.z; e1.w *= acc1[b].w + b1.w;
                *m4(wbuf + b * 256 + 8 * lane) = e0;
                *m4(wbuf + b * 256 + 8 * lane + 4) = e1;
            }
        }
        __syncwarp();   // t reads done before h-gather overwrites
        // gather h (float4)
        #pragma unroll
        for (int b = 0; b < 4; ++b) {
            const float4* hs = c4(g_h + (size_t)srcv[b] * 256);
            const float4* hd = c4(g_h + (size_t)dstv[b] * 256);
            m4(bufs + b * 256)[lane]      = hs[lane];
            m4(bufs + b * 256)[lane + 32] = hs[lane + 32];
            m4(bufd + b * 256)[lane]      = hd[lane];
            m4(bufd + b * 256)[lane + 32] = hd[lane + 32];
        }
        __syncwarp();

        // tensor product (u = 2*lane, 2*lane+1) + write g_pair
        #pragma unroll
        for (int b = 0; b < 4; ++b) {
            if (base + b >= E) continue;
            const float* xb = bufs + b * 256;
            const float* yb = bufd + b * 256;
            const float* wb = wbuf + b * 256;
            float2 xs = *c2(xb + 2 * lane), ys = *c2(yb + 2 * lane);
            const float* xe = xb + 64 + 6 * lane;
            const float* ye = yb + 64 + 6 * lane;
            float2 x01 = *c2(xe), x23 = *c2(xe + 2), x45 = *c2(xe + 4);
            float2 y01 = *c2(ye), y23 = *c2(ye + 2), y45 = *c2(ye + 4);
            float2 wss = *c2(wb + 2 * lane);
            float2 wsv = *c2(wb + 64 + 2 * lane);
            float2 wvs = *c2(wb + 128 + 2 * lane);
            float2 wvv = *c2(wb + 192 + 2 * lane);
            float dot0 = x01.x*y01.x + x01.y*y01.y + x23.x*y23.x;
            float dot1 = x23.y*y23.y + x45.x*y45.x + x45.y*y45.y;
            float* outp = g_pair + (size_t)(base + b) * 256;
            float2 os = { CSSf * wss.x * xs.x * ys.x + CVVf * wvv.x * dot0,
                          CSSf * wss.y * xs.y * ys.y + CVVf * wvv.y * dot1 };
            *m2(outp + 2 * lane) = os;
            float a0 = CSVf * wsv.x * xs.x, c0 = CSVf * wvs.x * ys.x;
            float a1 = CSVf * wsv.y * xs.y, c1 = CSVf * wvs.y * ys.y;
            float* ov = outp + 64 + 6 * lane;
            float2 o0 = { a0*y01.x + c0*x01.x, a0*y01.y + c0*x01.y };
            float2 o1 = { a0*y23.x + c0*x23.x, a1*y23.y + c1*x23.y };
            float2 o2 = { a1*y45.x + c1*x45.x, a1*y45.y + c1*x45.y };
            *m2(ov) = o0; *m2(ov + 2) = o1; *m2(ov + 4) = o2;
        }
        __syncwarp();
    }
}

// batched 128->128 matvec, 4 inputs stride 128 in shared, out mapping j=4*lane+r
template<bool ACT>
__device__ __forceinline__ void mv128_b4(const float* __restrict__ Ws,
                                         const float* __restrict__ in,   // 4 x 128
                                         const float* __restrict__ bs,
                                         float* __restrict__ out,        // 4 x 128
                                         int lane)
{
    int j = 4 * lane;
    float4 a[4];
    #pragma unroll
    for (int b = 0; b < 4; ++b) a[b] = make_float4(0,0,0,0);
    #pragma unroll 2
    for (int k4 = 0; k4 < 32; ++k4) {
        float4 w0 = *c4(Ws + (4*k4+0) * 128 + j);
        float4 w1 = *c4(Ws + (4*k4+1) * 128 + j);
        float4 w2 = *c4(Ws + (4*k4+2) * 128 + j);
        float4 w3 = *c4(Ws + (4*k4+3) * 128 + j);
        #pragma unroll
        for (int b = 0; b < 4; ++b) {
            float4 c = *c4(in + b * 128 + 4 * k4);
            a[b].x += c.x*w0.x + c.y*w1.x + c.z*w2.x + c.w*w3.x;
            a[b].y += c.x*w0.y + c.y*w1.y + c.z*w2.y + c.w*w3.y;
            a[b].z += c.x*w0.z + c.y*w1.z + c.z*w2.z + c.w*w3.z;
            a[b].w += c.x*w0.w + c.y*w1.w + c.z*w2.w + c.w*w3.w;
        }
    }
    float4 bb = *c4(bs + j);
    #pragma unroll
    for (int b = 0; b < 4; ++b) {
        float4 r = a[b];
        r.x += bb.x; r.y += bb.y; r.z += bb.z; r.w += bb.w;
        if (ACT) { r.x = silu_f(r.x); r.y = silu_f(r.y); r.z = silu_f(r.z); r.w = silu_f(r.w); }
        *m4(out + b * 128 + j) = r;
    }
}

// ======================= kernel 3: edge phase B (B=4, vectorized) =======================
__global__ void __launch_bounds__(256) edgeB_kernel(
    int E,
    const float* __restrict__ npa,
    const float* __restrict__ W1, const float* __restrict__ b1,
    const float* __restrict__ W2, const float* __restrict__ b2,
    const float* __restrict__ Wr0, const float* __restrict__ Wr1, const float* __restrict__ br0,
    float* __restrict__ out)
{
    extern __shared__ float sh[];
    float* sW1  = sh;             // 16384
    float* sW2  = sh + 16384;     // 16384
    float* sWr0 = sh + 32768;     // 4096
    float* sWr1 = sh + 36864;     // 4096
    float* sb   = sh + 40960;     // 320
    float* sstage = sh + 41280;   // 8 * 2048

    int tid = threadIdx.x;
    for (int i = tid; i < 16384; i += 256) { sW1[i] = W1[i]; sW2[i] = W2[i]; }
    for (int i = tid; i < 4096; i += 256)  { sWr0[i] = Wr0[i]; sWr1[i] = Wr1[i]; }
    if (tid < 128) { sb[tid] = b1[tid]; sb[128 + tid] = b2[tid]; }
    if (tid < 64)  sb[256 + tid] = br0[tid];
    __syncthreads();
    const float* sb1  = sb;
    const float* sb2  = sb + 128;
    const float* sbr0 = sb + 256;

    int warp = tid >> 5, lane = tid & 31;
    int gw = blockIdx.x * 8 + warp;
    int nwarps = gridDim.x * 8;
    float* st  = sstage + warp * 2048;
    float* p   = st;          // 4*256
    float* cat = st + 1024;   // 4*128 (later: gv)
    float* g1  = st + 1536;   // 4*128

    for (int base = gw * 4; base < E; base += nwarps * 4) {
        // load p (float4)
        #pragma unroll
        for (int b = 0; b < 4; ++b) {
            int e = min(base + b, E - 1);
            const float4* pg = c4(g_pair + (size_t)e * 256);
            m4(p + b * 256)[lane]      = pg[lane];
            m4(p + b * 256)[lane + 32] = pg[lane + 32];
        }
        __syncwarp();
        // cat = [s, |v|]   (u = 2*lane, 2*lane+1)
        #pragma unroll
        for (int b = 0; b < 4; ++b) {
            const float* pb = p + b * 256;
            float2 s = *c2(pb + 2 * lane);
            *m2(cat + b * 128 + 2 * lane) = s;
            const float* e = pb + 64 + 6 * lane;
            float2 e01 = *c2(e), e23 = *c2(e + 2), e45 = *c2(e + 4);
            float2 nn = { sqrtf(e01.x*e01.x + e01.y*e01.y + e23.x*e23.x),
                          sqrtf(e23.y*e23.y + e45.x*e45.x + e45.y*e45.y) };
            *m2(cat + b * 128 + 64 + 2 * lane) = nn;
        }
        __syncwarp();
        mv128_b4<true >(sW1, cat, sb1, g1, lane);
        __syncwarp();
        mv128_b4<false>(sW2, g1, sb2, cat, lane);   // gv overwrites cat
        __syncwarp();
        // gate p vector parts (gu from cat[64..127])
        #pragma unroll
        for (int b = 0; b < 4; ++b) {
            float2 g = *c2(cat + b * 128 + 64 + 2 * lane);
            float* e = p + b * 256 + 64 + 6 * lane;
            float2 e01 = *c2(e), e23 = *c2(e + 2), e45 = *c2(e + 4);
            e01.x *= g.x; e01.y *= g.x;
            e23.x *= g.x; e23.y *= g.y;
            e45.x *= g.y; e45.y *= g.y;
            *m2(e) = e01; *m2(e + 2) = e23; *m2(e + 4) = e45;
        }
        __syncwarp();
        // final e3nn + residual
        {
            // scalar: out cols j = 2*lane, 2*lane+1
            int j = 2 * lane;
            float ax[4] = {0,0,0,0}, ay[4] = {0,0,0,0};
            #pragma unroll 4
            for (int u2 = 0; u2 < 32; ++u2) {
                float2 w0 = *c2(sWr0 + (2*u2) * 64 + j);
                float2 w1 = *c2(sWr0 + (2*u2+1) * 64 + j);
                #pragma unroll
                for (int b = 0; b < 4; ++b) {
                    float2 c = *c2(cat + b * 128 + 2 * u2);
                    ax[b] += c.x * w0.x + c.y * w1.x;
                    ay[b] += c.x * w0.y + c.y * w1.y;
                }
            }
            float2 bb = *c2(sbr0 + j);
            #pragma unroll
            for (int b = 0; b < 4; ++b) {
                if (base + b >= E) continue;
                const float* np = npa + (size_t)(base + b) * 256;
                float* og = out + (size_t)(base + b) * 256;
                float2 nv = *c2(np + j);
                float2 os = { ax[b] * INV8f + bb.x + nv.x, ay[b] * INV8f + bb.y + nv.y };
                *m2(og + j) = os;
            }
            // vector: out cols j, j+1 -> writes 6 consecutive floats at 64+6*lane
            float v[4][6];
            #pragma unroll
            for (int b = 0; b < 4; ++b)
                #pragma unroll
                for (int r = 0; r < 6; ++r) v[b][r] = 0.f;
            #pragma unroll 2
            for (int u2 = 0; u2 < 32; ++u2) {
                float2 w0 = *c2(sWr1 + (2*u2) * 64 + j);
                float2 w1 = *c2(sWr1 + (2*u2+1) * 64 + j);
                #pragma unroll
                for (int b = 0; b < 4; ++b) {
                    const float* e = p + b * 256 + 64 + 6 * u2;
                    float2 e01 = *c2(e), e23 = *c2(e + 2), e45 = *c2(e + 4);
                    v[b][0] += e01.x * w0.x + e23.y * w1.x;
                    v[b][1] += e01.y * w0.x + e45.x * w1.x;
                    v[b][2] += e23.x * w0.x + e45.y * w1.x;
                    v[b][3] += e01.x * w0.y + e23.y * w1.y;
                    v[b][4] += e01.y * w0.y + e45.x * w1.y;
                    v[b][5] += e23.x * w0.y + e45.y * w1.y;
                }
            }
            #pragma unroll
            for (int b = 0; b < 4; ++b) {
                if (base + b >= E) continue;
                const float* np = npa + (size_t)(base + b) * 256 + 64 + 6 * lane;
                float* og = out + (size_t)(base + b) * 256 + 64 + 6 * lane;
                float2 n0v = *c2(np), n1v = *c2(np + 2), n2v = *c2(np + 4);
                float2 o0 = { v[b][0] * INV8f + n0v.x, v[b][1] * INV8f + n0v.y };
                float2 o1 = { v[b][2] * INV8f + n1v.x, v[b][3] * INV8f + n1v.y };
                float2 o2 = { v[b][4] * INV8f + n2v.x, v[b][5] * INV8f + n2v.y };
                *m2(og) = o0; *m2(og + 2) = o1; *m2(og + 4) = o2;
            }
        }
        __syncwarp();
    }
}

// ======================= launcher =======================
extern "C" void kernel_launch(void* const* d_in, const int* in_sizes, int n_in,
                              void* d_out, int out_size)
{
    const float* node_attr = (const float*)d_in[0];
    const int*   eidx      = (const int*)  d_in[1];
    const float* edge_attr = (const float*)d_in[2];
    const float* npa       = (const float*)d_in[3];
    const float* Wli0 = (const float*)d_in[4];
    const float* Wli1 = (const float*)d_in[5];
    const float* bli0 = (const float*)d_in[6];
    const float* ng1_W1 = (const float*)d_in[7];
    const float* ng1_b1 = (const float*)d_in[8];
    const float* ng1_W2 = (const float*)d_in[9];
    const float* ng1_b2 = (const float*)d_in[10];
    const float* Wlp0 = (const float*)d_in[11];
    const float* Wlp1 = (const float*)d_in[12];
    const float* blp0 = (const float*)d_in[13];
    const float* Wfc1 = (const float*)d_in[14];
    const float* Wfc2 = (const float*)d_in[15];
    const float* A1   = (const float*)d_in[16];
    const float* a1b  = (const float*)d_in[17];
    const float* A2   = (const float*)d_in[18];
    const float* a2b  = (const float*)d_in[19];
    const float* ng2_W1 = (const float*)d_in[20];
    const float* ng2_b1 = (const float*)d_in[21];
    const float* ng2_W2 = (const float*)d_in[22];
    const float* ng2_b2 = (const float*)d_in[23];
    const float* Wr0  = (const float*)d_in[24];
    const float* Wr1  = (const float*)d_in[25];
    const float* br0  = (const float*)d_in[26];
    float* out = (float*)d_out;

    int N = in_sizes[0] / 256;
    int E = in_sizes[1] / 2;

    size_t shN = (size_t)(49536 + 8 * 1024) * sizeof(float);   // 230912 B
    size_t shA = (size_t)(27200 + 8 * 3072) * sizeof(float);   // 207104 B
    size_t shB = (size_t)(41280 + 8 * 2048) * sizeof(float);   // 230656 B

    cudaFuncSetAttribute(node_kernel,  cudaFuncAttributeMaxDynamicSharedMemorySize, (int)shN);
    cudaFuncSetAttribute(edgeA_kernel, cudaFuncAttributeMaxDynamicSharedMemorySize, (int)shA);
    cudaFuncSetAttribute(edgeB_kernel, cudaFuncAttributeMaxDynamicSharedMemorySize, (int)shB);

    node_kernel<<<148, 256, shN>>>(node_attr, N, Wli0, Wli1, bli0,
                                   ng1_W1, ng1_b1, ng1_W2, ng1_b2,
                                   Wlp0, Wlp1, blp0);
    edgeA_kernel<<<148, 256, shA>>>(eidx, E, edge_attr, A1, a1b, A2, a2b, Wfc1, Wfc2);
    edgeB_kernel<<<148, 256, shB>>>(E, npa, ng2_W1, ng2_b1, ng2_W2, ng2_b2,
                                    Wr0, Wr1, br0, out);
}